// round 14
// baseline (speedup 1.0000x reference)
#include <cuda_runtime.h>
#include <cuda_fp16.h>
#include <stdint.h>

// Attention_49194555408812: mma.sync fp16 single-pass, sm_103-safe.
// Round 14: R8 main kernel verbatim (best: 107.2us) + Q conversion fused into
// the main kernel prologue (prepass now converts only K/V: 72MB -> 48MB traffic).
// exp2-folded fp32 softmax, deferred rsum, 3 CTAs/SM, 3-stage ring.

namespace {
constexpr int D   = 64;
constexpr int LEN = 2048;
constexpr int BH  = 32;
constexpr int TQ  = 64;
constexpr int TK  = 64;
constexpr int NT  = LEN / TK;   // 32
constexpr float QSCALE = 0.125f * 1.4426950408889634f;   // 1/sqrt(64) * log2(e)
constexpr float NSLOPE = 0.01f;
constexpr int NELEM = BH * D * LEN;

constexpr int OFF_Q  = 0;                   // [d=64][q=64] fp16, 128B rows (8KB)
constexpr int OFF_ST = 8192;                // 3 stages x 16KB
constexpr int STAGE  = 16384;
constexpr int A_KH = 0, A_VH = 8192;
constexpr int SMEM_TOTAL = OFF_ST + 3 * STAGE;   // 56 KB (3 CTAs/SM)
constexpr int OPITCH = 68;                  // padded f32 pitch
}  // namespace

__device__ __align__(16) __half g_k[NELEM], g_v[NELEM];

__device__ __forceinline__ uint32_t swz128(uint32_t o) { return o ^ ((o >> 3) & 0x70); }

__device__ __forceinline__ uint32_t smem_u32(const void* p) {
    uint32_t a;
    asm("{ .reg .u64 t; cvta.to.shared.u64 t, %1; cvt.u32.u64 %0, t; }" : "=r"(a) : "l"(p));
    return a;
}
__device__ __forceinline__ void ldsm_x4_t(uint32_t addr, uint32_t& r0, uint32_t& r1,
                                          uint32_t& r2, uint32_t& r3) {
    asm volatile("ldmatrix.sync.aligned.m8n8.x4.trans.shared.b16 {%0,%1,%2,%3}, [%4];"
                 : "=r"(r0), "=r"(r1), "=r"(r2), "=r"(r3) : "r"(addr));
}
__device__ __forceinline__ void ldsm_x4(uint32_t addr, uint32_t& r0, uint32_t& r1,
                                        uint32_t& r2, uint32_t& r3) {
    asm volatile("ldmatrix.sync.aligned.m8n8.x4.shared.b16 {%0,%1,%2,%3}, [%4];"
                 : "=r"(r0), "=r"(r1), "=r"(r2), "=r"(r3) : "r"(addr));
}
__device__ __forceinline__ void mma16816(float c[4], const uint32_t a[4],
                                         uint32_t b0, uint32_t b1) {
    asm volatile(
        "mma.sync.aligned.m16n8k16.row.col.f32.f16.f16.f32 "
        "{%0,%1,%2,%3}, {%4,%5,%6,%7}, {%8,%9}, {%0,%1,%2,%3};"
        : "+f"(c[0]), "+f"(c[1]), "+f"(c[2]), "+f"(c[3])
        : "r"(a[0]), "r"(a[1]), "r"(a[2]), "r"(a[3]), "r"(b0), "r"(b1));
}
__device__ __forceinline__ uint32_t h2_bits(float a, float b) {
    __half2 h = __floats2half2_rn(a, b);
    return *reinterpret_cast<uint32_t*>(&h);
}
__device__ __forceinline__ float ex2(float x) {
    float y;
    asm("ex2.approx.f32 %0, %1;" : "=f"(y) : "f"(x));
    return y;
}

#define CP_ASYNC16(dst, src) \
    asm volatile("cp.async.cg.shared.global [%0], [%1], 16;" :: "r"(dst), "l"(src) : "memory")
#define CP_COMMIT() asm volatile("cp.async.commit_group;" ::: "memory")
#define CP_WAIT1()  asm volatile("cp.async.wait_group 1;" ::: "memory")

// ------------- pre-pass: K,V -> fp16 only (Q fused into main kernel) -------------
__global__ void convert_split(const float* __restrict__ k, const float* __restrict__ v) {
    const int NV4 = NELEM / 4;
    for (int i = blockIdx.x * blockDim.x + threadIdx.x; i < 2 * NV4;
         i += gridDim.x * blockDim.x) {
        const int t = i / NV4, j = i - t * NV4;
        const float* src = (t == 0) ? k : v;
        __half* dst = (t == 0) ? g_k : g_v;
        float4 f = reinterpret_cast<const float4*>(src)[j];
        reinterpret_cast<uint2*>(dst)[j] =
            make_uint2(h2_bits(f.x, f.y), h2_bits(f.z, f.w));
    }
}

// ---------------- main kernel ----------------
__device__ __forceinline__ void issue_tile(uint32_t sbase, size_t hbase, int kt, int tid) {
    const __half* gsrc[2] = {g_k, g_v};
#pragma unroll
    for (int a = 0; a < 2; ++a) {
#pragma unroll
        for (int c = 0; c < 4; ++c) {
            const int ci = c * 128 + tid;        // 512 chunks of 16B per array
            const int d = ci >> 3, c8 = ci & 7;
            const void* src = gsrc[a] + hbase + (size_t)d * LEN + kt + c8 * 8;
            CP_ASYNC16(sbase + a * 8192 + swz128(d * 128 + c8 * 16), src);
        }
    }
}

__global__ void __launch_bounds__(128, 3)
attn_mma(const float* __restrict__ qg, float* __restrict__ outg) {
    extern __shared__ __align__(1024) char smem[];
    const uint32_t sb = smem_u32(smem);

    const int tid  = threadIdx.x;
    const int wid  = tid >> 5;
    const int lane = tid & 31;
    const int sub  = lane >> 3;
    const int li   = lane & 7;
    const int bh   = blockIdx.y;
    const int qt   = blockIdx.x * TQ;
    const size_t base = (size_t)bh * D * LEN;

    // prologue: kick off K/V tile0 (group0), tile1 (group1) FIRST, then convert Q
    issue_tile(sb + OFF_ST, base, 0, tid);
    CP_COMMIT();
    issue_tile(sb + OFF_ST + STAGE, base, TK, tid);
    CP_COMMIT();

    // Q: load f32, scale by 1/8*log2e, convert to fp16, store swizzled.
    // 1024 float4 chunks; 8 per thread. Overlaps with cp.async flight.
#pragma unroll
    for (int c = 0; c < 8; ++c) {
        const int ci = c * 128 + tid;
        const int d = ci >> 4, c4 = ci & 15;
        float4 f = *reinterpret_cast<const float4*>(qg + base + (size_t)d * LEN + qt + c4 * 4);
        f.x *= QSCALE; f.y *= QSCALE; f.z *= QSCALE; f.w *= QSCALE;
        *reinterpret_cast<uint2*>(smem + OFF_Q + swz128(d * 128 + c4 * 8)) =
            make_uint2(h2_bits(f.x, f.y), h2_bits(f.z, f.w));
    }

    CP_WAIT1();
    __syncthreads();

    // Q fragments (one-time): one m16 block per warp
    uint32_t Qf[4][4];
    {
        const int q0 = wid * 16 + ((sub & 1) << 3);
#pragma unroll
        for (int j = 0; j < 4; ++j) {
            const int dr = 16 * j + ((sub >> 1) << 3) + li;
            ldsm_x4_t(sb + OFF_Q + swz128(dr * 128 + q0 * 2),
                      Qf[j][0], Qf[j][1], Qf[j][2], Qf[j][3]);
        }
    }

    float O[8][4];
#pragma unroll
    for (int n = 0; n < 8; ++n)
#pragma unroll
        for (int c = 0; c < 4; ++c) O[n][c] = 0.0f;
    float rsum0 = 0.0f, rsum1 = 0.0f;

    int stg_idx = 0;
    for (int t = 0; t < NT; ++t) {
        if (t) { CP_WAIT1(); __syncthreads(); }
        const uint32_t stg = sb + OFF_ST + stg_idx * STAGE;

        // prefetch t+2 into stage (t-1)%3 (readers done before barrier above)
        if (t + 2 < NT)
            issue_tile(sb + OFF_ST + ((stg_idx + 2) % 3) * STAGE, base, (t + 2) * TK, tid);
        CP_COMMIT();                              // uniform group count

        // ---- GEMM1: S' = Q·K (full tile, max ILP) ----
        float S[8][4];
#pragma unroll
        for (int n = 0; n < 8; ++n)
#pragma unroll
            for (int c = 0; c < 4; ++c) S[n][c] = 0.0f;
#pragma unroll
        for (int j = 0; j < 4; ++j) {
            const int dr = 16 * j + ((sub & 1) << 3) + li;
#pragma unroll
            for (int np = 0; np < 4; ++np) {
                const int nc = 16 * np + ((sub >> 1) << 3);
                uint32_t b0, b1, b2, b3;
                ldsm_x4_t(stg + A_KH + swz128(dr * 128 + nc * 2), b0, b1, b2, b3);
                mma16816(S[2 * np],     Qf[j], b0, b1);
                mma16816(S[2 * np + 1], Qf[j], b2, b3);
            }
        }

        // ---- p = 2^(leakyrelu(s')); per-thread partial sums ----
        float t0 = 0.0f, t1 = 0.0f;
#pragma unroll
        for (int n = 0; n < 8; ++n) {
#pragma unroll
            for (int c = 0; c < 4; ++c) {
                float x = S[n][c];
                S[n][c] = ex2(fmaxf(x, NSLOPE * x));
            }
            t0 += S[n][0] + S[n][1];
            t1 += S[n][2] + S[n][3];
        }
        rsum0 += t0;
        rsum1 += t1;

        // ---- GEMM2: O += P·V (single fp16 pass, in-register repack) ----
#pragma unroll
        for (int j = 0; j < 4; ++j) {
            uint32_t ah[4];
            ah[0] = h2_bits(S[2 * j][0],     S[2 * j][1]);
            ah[1] = h2_bits(S[2 * j][2],     S[2 * j][3]);
            ah[2] = h2_bits(S[2 * j + 1][0], S[2 * j + 1][1]);
            ah[3] = h2_bits(S[2 * j + 1][2], S[2 * j + 1][3]);
            const int kc = 16 * j + ((sub & 1) << 3);
#pragma unroll
            for (int dp = 0; dp < 4; ++dp) {
                const int dr = 16 * dp + ((sub >> 1) << 3) + li;
                uint32_t b0, b1, b2, b3;
                ldsm_x4(stg + A_VH + swz128(dr * 128 + kc * 2), b0, b1, b2, b3);
                mma16816(O[2 * dp],     ah, b0, b1);
                mma16816(O[2 * dp + 1], ah, b2, b3);
            }
        }

        stg_idx = (stg_idx + 1) % 3;
    }

    // ---- deferred quad reduction of row sums ----
    rsum0 += __shfl_xor_sync(0xffffffffu, rsum0, 1);
    rsum0 += __shfl_xor_sync(0xffffffffu, rsum0, 2);
    rsum1 += __shfl_xor_sync(0xffffffffu, rsum1, 1);
    rsum1 += __shfl_xor_sync(0xffffffffu, rsum1, 2);

    // ---- epilogue: stage O in smem (padded pitch), coalesced float4 stores ----
    __syncthreads();
    float* Obuf = reinterpret_cast<float*>(smem + OFF_ST);
    const float inv0 = 1.0f / rsum0;
    const float inv1 = 1.0f / rsum1;
    const int qc = wid * 16 + (lane >> 2);
#pragma unroll
    for (int n = 0; n < 8; ++n) {
        const int d0 = 8 * n + 2 * (lane & 3);
        Obuf[d0 * OPITCH + qc]           = O[n][0] * inv0;
        Obuf[(d0 + 1) * OPITCH + qc]     = O[n][1] * inv0;
        Obuf[d0 * OPITCH + qc + 8]       = O[n][2] * inv1;
        Obuf[(d0 + 1) * OPITCH + qc + 8] = O[n][3] * inv1;
    }
    __syncthreads();
#pragma unroll
    for (int i = 0; i < 8; ++i) {
        const int idx = i * 128 + tid;            // 1024 float4 total
        const int row = idx >> 4, c4 = idx & 15;
        float4 val = *reinterpret_cast<const float4*>(Obuf + row * OPITCH + c4 * 4);
        *reinterpret_cast<float4*>(outg + base + (size_t)row * LEN + qt + c4 * 4) = val;
    }
}

extern "C" void kernel_launch(void* const* d_in, const int* in_sizes, int n_in,
                              void* d_out, int out_size) {
    const float* q = (const float*)d_in[0];
    const float* k = (const float*)d_in[1];
    const float* v = (const float*)d_in[2];
    float* out = (float*)d_out;

    convert_split<<<1024, 256>>>(k, v);

    cudaFuncSetAttribute(attn_mma, cudaFuncAttributeMaxDynamicSharedMemorySize, SMEM_TOTAL);
    dim3 grid(LEN / TQ, BH);                      // (32, 32) = 1024 CTAs
    attn_mma<<<grid, 128, SMEM_TOTAL>>>(q, out);
}

// round 15
// speedup vs baseline: 1.0981x; 1.0981x over previous
#include <cuda_runtime.h>
#include <cuda_fp16.h>
#include <stdint.h>

// Attention_49194555408812: mma.sync fp16 single-pass, sm_103-safe.
// Round 15: R8 (best config: TQ=64, 4 warps, 3 CTAs/SM, 3-stage ring, prepass
// converts Q/K/V) + interleaved softmax/GEMM2: exp+repack of each n-pair j is
// fused into GEMM2's j-loop (8 MUFU -> 16 HMMA repeating) for pipe diversity.

namespace {
constexpr int D   = 64;
constexpr int LEN = 2048;
constexpr int BH  = 32;
constexpr int TQ  = 64;
constexpr int TK  = 64;
constexpr int NT  = LEN / TK;   // 32
constexpr float QSCALE = 0.125f * 1.4426950408889634f;   // 1/sqrt(64) * log2(e)
constexpr float NSLOPE = 0.01f;
constexpr int NELEM = BH * D * LEN;

constexpr int OFF_Q  = 0;                   // [d=64][q=64] fp16, 128B rows (8KB)
constexpr int OFF_ST = 8192;                // 3 stages x 16KB
constexpr int STAGE  = 16384;
constexpr int A_KH = 0, A_VH = 8192;
constexpr int SMEM_TOTAL = OFF_ST + 3 * STAGE;   // 56 KB (3 CTAs/SM)
constexpr int OPITCH = 68;                  // padded f32 pitch
}  // namespace

__device__ __align__(16) __half g_q[NELEM];
__device__ __align__(16) __half g_k[NELEM], g_v[NELEM];

__device__ __forceinline__ uint32_t swz128(uint32_t o) { return o ^ (((o) >> 3) & 0x70); }

__device__ __forceinline__ uint32_t smem_u32(const void* p) {
    uint32_t a;
    asm("{ .reg .u64 t; cvta.to.shared.u64 t, %1; cvt.u32.u64 %0, t; }" : "=r"(a) : "l"(p));
    return a;
}
__device__ __forceinline__ void ldsm_x4_t(uint32_t addr, uint32_t& r0, uint32_t& r1,
                                          uint32_t& r2, uint32_t& r3) {
    asm volatile("ldmatrix.sync.aligned.m8n8.x4.trans.shared.b16 {%0,%1,%2,%3}, [%4];"
                 : "=r"(r0), "=r"(r1), "=r"(r2), "=r"(r3) : "r"(addr));
}
__device__ __forceinline__ void ldsm_x4(uint32_t addr, uint32_t& r0, uint32_t& r1,
                                        uint32_t& r2, uint32_t& r3) {
    asm volatile("ldmatrix.sync.aligned.m8n8.x4.shared.b16 {%0,%1,%2,%3}, [%4];"
                 : "=r"(r0), "=r"(r1), "=r"(r2), "=r"(r3) : "r"(addr));
}
__device__ __forceinline__ void mma16816(float c[4], const uint32_t a[4],
                                         uint32_t b0, uint32_t b1) {
    asm volatile(
        "mma.sync.aligned.m16n8k16.row.col.f32.f16.f16.f32 "
        "{%0,%1,%2,%3}, {%4,%5,%6,%7}, {%8,%9}, {%0,%1,%2,%3};"
        : "+f"(c[0]), "+f"(c[1]), "+f"(c[2]), "+f"(c[3])
        : "r"(a[0]), "r"(a[1]), "r"(a[2]), "r"(a[3]), "r"(b0), "r"(b1));
}
__device__ __forceinline__ uint32_t h2_bits(float a, float b) {
    __half2 h = __floats2half2_rn(a, b);
    return *reinterpret_cast<uint32_t*>(&h);
}
__device__ __forceinline__ float ex2(float x) {
    float y;
    asm("ex2.approx.f32 %0, %1;" : "=f"(y) : "f"(x));
    return y;
}

#define CP_ASYNC16(dst, src) \
    asm volatile("cp.async.cg.shared.global [%0], [%1], 16;" :: "r"(dst), "l"(src) : "memory")
#define CP_COMMIT() asm volatile("cp.async.commit_group;" ::: "memory")
#define CP_WAIT1()  asm volatile("cp.async.wait_group 1;" ::: "memory")

// ------------- pre-pass: Q -> fp16 (scaled by 1/8*log2e); K,V -> fp16 -------------
__global__ void convert_split(const float* __restrict__ q, const float* __restrict__ k,
                              const float* __restrict__ v) {
    const int NV4 = NELEM / 4;
    for (int i = blockIdx.x * blockDim.x + threadIdx.x; i < 3 * NV4;
         i += gridDim.x * blockDim.x) {
        const int t = i / NV4, j = i - t * NV4;
        const float* src = (t == 0) ? q : (t == 1) ? k : v;
        __half* dst = (t == 0) ? g_q : (t == 1) ? g_k : g_v;
        float4 f = reinterpret_cast<const float4*>(src)[j];
        if (t == 0) { f.x *= QSCALE; f.y *= QSCALE; f.z *= QSCALE; f.w *= QSCALE; }
        reinterpret_cast<uint2*>(dst)[j] =
            make_uint2(h2_bits(f.x, f.y), h2_bits(f.z, f.w));
    }
}

// ---------------- main kernel ----------------
__device__ __forceinline__ void issue_tile(uint32_t sbase, size_t hbase, int kt, int tid) {
    const __half* gsrc[2] = {g_k, g_v};
#pragma unroll
    for (int a = 0; a < 2; ++a) {
#pragma unroll
        for (int c = 0; c < 4; ++c) {
            const int ci = c * 128 + tid;        // 512 chunks of 16B per array
            const int d = ci >> 3, c8 = ci & 7;
            const void* src = gsrc[a] + hbase + (size_t)d * LEN + kt + c8 * 8;
            CP_ASYNC16(sbase + a * 8192 + swz128(d * 128 + c8 * 16), src);
        }
    }
}

__global__ void __launch_bounds__(128, 3)
attn_mma(float* __restrict__ outg) {
    extern __shared__ __align__(1024) char smem[];
    const uint32_t sb = smem_u32(smem);

    const int tid  = threadIdx.x;
    const int wid  = tid >> 5;
    const int lane = tid & 31;
    const int sub  = lane >> 3;
    const int li   = lane & 7;
    const int bh   = blockIdx.y;
    const int qt   = blockIdx.x * TQ;
    const size_t base = (size_t)bh * D * LEN;

    // prologue: Q + tile0 as group0; tile1 as group1
    {
#pragma unroll
        for (int c = 0; c < 4; ++c) {
            const int ci = c * 128 + tid;
            const int d = ci >> 3, c8 = ci & 7;
            const void* src = g_q + base + (size_t)d * LEN + qt + c8 * 8;
            CP_ASYNC16(sb + OFF_Q + swz128(d * 128 + c8 * 16), src);
        }
        issue_tile(sb + OFF_ST, base, 0, tid);
        CP_COMMIT();
        issue_tile(sb + OFF_ST + STAGE, base, TK, tid);
        CP_COMMIT();
    }
    CP_WAIT1();
    __syncthreads();

    // Q fragments (one-time): one m16 block per warp
    uint32_t Qf[4][4];
    {
        const int q0 = wid * 16 + ((sub & 1) << 3);
#pragma unroll
        for (int j = 0; j < 4; ++j) {
            const int dr = 16 * j + ((sub >> 1) << 3) + li;
            ldsm_x4_t(sb + OFF_Q + swz128(dr * 128 + q0 * 2),
                      Qf[j][0], Qf[j][1], Qf[j][2], Qf[j][3]);
        }
    }

    float O[8][4];
#pragma unroll
    for (int n = 0; n < 8; ++n)
#pragma unroll
        for (int c = 0; c < 4; ++c) O[n][c] = 0.0f;
    float rsum0 = 0.0f, rsum1 = 0.0f;

    int stg_idx = 0;
    for (int t = 0; t < NT; ++t) {
        if (t) { CP_WAIT1(); __syncthreads(); }
        const uint32_t stg = sb + OFF_ST + stg_idx * STAGE;

        // prefetch t+2 into stage (t-1)%3 (its readers finished before the barrier)
        if (t + 2 < NT)
            issue_tile(sb + OFF_ST + ((stg_idx + 2) % 3) * STAGE, base, (t + 2) * TK, tid);
        CP_COMMIT();                              // uniform group count

        // ---- GEMM1: S' = Q·K (full tile, max ILP) ----
        float S[8][4];
#pragma unroll
        for (int n = 0; n < 8; ++n)
#pragma unroll
            for (int c = 0; c < 4; ++c) S[n][c] = 0.0f;
#pragma unroll
        for (int j = 0; j < 4; ++j) {
            const int dr = 16 * j + ((sub & 1) << 3) + li;
#pragma unroll
            for (int np = 0; np < 4; ++np) {
                const int nc = 16 * np + ((sub >> 1) << 3);
                uint32_t b0, b1, b2, b3;
                ldsm_x4_t(stg + A_KH + swz128(dr * 128 + nc * 2), b0, b1, b2, b3);
                mma16816(S[2 * np],     Qf[j], b0, b1);
                mma16816(S[2 * np + 1], Qf[j], b2, b3);
            }
        }

        // ---- interleaved softmax + GEMM2: per n-pair j, 8 MUFU then 16 HMMA ----
#pragma unroll
        for (int j = 0; j < 4; ++j) {
            // exp of this pair's 8 score values (pure code motion vs R8)
#pragma unroll
            for (int n = 2 * j; n < 2 * j + 2; ++n) {
#pragma unroll
                for (int c = 0; c < 4; ++c) {
                    float x = S[n][c];
                    S[n][c] = ex2(fmaxf(x, NSLOPE * x));
                }
                rsum0 += S[n][0] + S[n][1];
                rsum1 += S[n][2] + S[n][3];
            }
            uint32_t ah[4];
            ah[0] = h2_bits(S[2 * j][0],     S[2 * j][1]);
            ah[1] = h2_bits(S[2 * j][2],     S[2 * j][3]);
            ah[2] = h2_bits(S[2 * j + 1][0], S[2 * j + 1][1]);
            ah[3] = h2_bits(S[2 * j + 1][2], S[2 * j + 1][3]);
            const int kc = 16 * j + ((sub & 1) << 3);
#pragma unroll
            for (int dp = 0; dp < 4; ++dp) {
                const int dr = 16 * dp + ((sub >> 1) << 3) + li;
                uint32_t b0, b1, b2, b3;
                ldsm_x4(stg + A_VH + swz128(dr * 128 + kc * 2), b0, b1, b2, b3);
                mma16816(O[2 * dp],     ah, b0, b1);
                mma16816(O[2 * dp + 1], ah, b2, b3);
            }
        }

        stg_idx = (stg_idx + 1) % 3;
    }

    // ---- deferred quad reduction of row sums ----
    rsum0 += __shfl_xor_sync(0xffffffffu, rsum0, 1);
    rsum0 += __shfl_xor_sync(0xffffffffu, rsum0, 2);
    rsum1 += __shfl_xor_sync(0xffffffffu, rsum1, 1);
    rsum1 += __shfl_xor_sync(0xffffffffu, rsum1, 2);

    // ---- epilogue: stage O in smem (padded pitch), coalesced float4 stores ----
    __syncthreads();
    float* Obuf = reinterpret_cast<float*>(smem + OFF_ST);
    const float inv0 = 1.0f / rsum0;
    const float inv1 = 1.0f / rsum1;
    const int qc = wid * 16 + (lane >> 2);
#pragma unroll
    for (int n = 0; n < 8; ++n) {
        const int d0 = 8 * n + 2 * (lane & 3);
        Obuf[d0 * OPITCH + qc]           = O[n][0] * inv0;
        Obuf[(d0 + 1) * OPITCH + qc]     = O[n][1] * inv0;
        Obuf[d0 * OPITCH + qc + 8]       = O[n][2] * inv1;
        Obuf[(d0 + 1) * OPITCH + qc + 8] = O[n][3] * inv1;
    }
    __syncthreads();
#pragma unroll
    for (int i = 0; i < 8; ++i) {
        const int idx = i * 128 + tid;            // 1024 float4 total
        const int row = idx >> 4, c4 = idx & 15;
        float4 val = *reinterpret_cast<const float4*>(Obuf + row * OPITCH + c4 * 4);
        *reinterpret_cast<float4*>(outg + base + (size_t)row * LEN + qt + c4 * 4) = val;
    }
}

extern "C" void kernel_launch(void* const* d_in, const int* in_sizes, int n_in,
                              void* d_out, int out_size) {
    const float* q = (const float*)d_in[0];
    const float* k = (const float*)d_in[1];
    const float* v = (const float*)d_in[2];
    float* out = (float*)d_out;

    convert_split<<<1024, 256>>>(q, k, v);

    cudaFuncSetAttribute(attn_mma, cudaFuncAttributeMaxDynamicSharedMemorySize, SMEM_TOTAL);
    dim3 grid(LEN / TQ, BH);                      // (32, 32) = 1024 CTAs
    attn_mma<<<grid, 128, SMEM_TOTAL>>>(out);
}